// round 1
// baseline (speedup 1.0000x reference)
#include <cuda_runtime.h>
#include <math.h>

#define TT 512
#define BB 64
#define II 128
#define HH 1024
#define KC 128
#define PSTR 132   // padded smem row stride (floats)

// Double-buffered hidden states (read parity = step&1, write parity = step&1^1)
__device__ float g_h0[2][BB * HH];
__device__ float g_h1[2][BB * HH];

typedef unsigned long long ull;

__device__ __forceinline__ ull pack2(float x, float y) {
    ull r; asm("mov.b64 %0, {%1, %2};" : "=l"(r) : "f"(x), "f"(y)); return r;
}
__device__ __forceinline__ ull ffma2(ull a, ull b, ull c) {
    ull d; asm("fma.rn.f32x2 %0, %1, %2, %3;" : "=l"(d) : "l"(a), "l"(b), "l"(c)); return d;
}
__device__ __forceinline__ float hsum2(ull v) {
    float x, y; asm("mov.b64 {%0, %1}, %2;" : "=f"(x), "=f"(y) : "l"(v)); return x + y;
}

__global__ void __launch_bounds__(256, 1) init_kernel() {
    int tid = blockIdx.x * blockDim.x + threadIdx.x;
    float* p0 = &g_h0[0][0];
    float* p1 = &g_h1[0][0];
    const int n = 2 * BB * HH;
    for (int i = tid; i < n; i += gridDim.x * blockDim.x) {
        p0[i] = 0.0f;
        p1[i] = 0.0f;
    }
}

// One pipeline phase: blocks 0..63 run layer0 at time t=ph (if ph<TT),
// blocks 64..127 run layer1 at time t=ph-1 (if ph>=1).
// Each block computes a [32 x 32] output tile (b-tile x j-tile), K streamed
// in 128-wide chunks via register-staged prefetch -> smem -> f32x2 FMAs.
// Thread org: 256 = 4 k-slices x (8 ty x 8 tx); per-thread 4x4 register tile.
__global__ void __launch_bounds__(256, 1) step_kernel(
    const float* __restrict__ x,
    const float* __restrict__ Win0,
    const float* __restrict__ What0,
    const float* __restrict__ Win1,
    const float* __restrict__ What1,
    float* __restrict__ out,
    int ph)
{
    __shared__ float smem[2 * 32 * PSTR];   // 33792 B; reduction aliases front
    float* sA = smem;
    float* sW = smem + 32 * PSTR;

    const int blk = blockIdx.x;
    const int layer = (blk >= 64) ? 1 : 0;
    const int id = layer ? (blk - 64) : blk;
    const int b0 = (id & 1) * 32;
    const int j0 = (id >> 1) * 32;

    int step;
    if (!layer) { if (ph >= TT) return; step = ph; }
    else        { if (ph == 0)  return; step = ph - 1; }

    const int tid = threadIdx.x;
    const int ks  = tid >> 6;        // k-slice 0..3
    const int lid = tid & 63;
    const int ty  = lid >> 3;        // 0..7
    const int tx  = lid & 7;         // 0..7

    const int par = step & 1;
    const float* hread  = layer ? g_h1[par]     : g_h0[par];
    float*       hwrite = layer ? g_h1[par ^ 1] : g_h0[par ^ 1];

    const int NC = layer ? 16 : 9;   // K chunks of 128

    // staging addressing: 4 x float4 per thread, coalesced over the 32x128 chunk
    int rows[4], cols[4];
#pragma unroll
    for (int w = 0; w < 4; ++w) {
        int flat = w * 1024 + tid * 4;
        rows[w] = flat >> 7;
        cols[w] = flat & 127;
    }

    float4 rA[4], rW[4];

    auto load_chunk = [&](int c) {
        const float* aptr; int astr;
        const float* wptr; int wstr;
        if (!layer) {
            if (c == 0) { aptr = x + (size_t)(step * BB + b0) * II;            astr = II;
                          wptr = Win0 + (size_t)j0 * II;                        wstr = II; }
            else        { aptr = hread + b0 * HH + (c - 1) * KC;                astr = HH;
                          wptr = What0 + (size_t)j0 * HH + (c - 1) * KC;        wstr = HH; }
        } else {
            if (c < 8)  { aptr = out + (size_t)(step * BB + b0) * 2 * HH + c * KC; astr = 2 * HH;
                          wptr = Win1 + (size_t)j0 * HH + c * KC;               wstr = HH; }
            else        { aptr = hread + b0 * HH + (c - 8) * KC;                astr = HH;
                          wptr = What1 + (size_t)j0 * HH + (c - 8) * KC;        wstr = HH; }
        }
#pragma unroll
        for (int w = 0; w < 4; ++w) {
            rA[w] = *reinterpret_cast<const float4*>(aptr + (size_t)rows[w] * astr + cols[w]);
            rW[w] = *reinterpret_cast<const float4*>(wptr + (size_t)rows[w] * wstr + cols[w]);
        }
    };

    load_chunk(0);

    ull acc[4][4];
#pragma unroll
    for (int r = 0; r < 4; ++r)
#pragma unroll
        for (int s = 0; s < 4; ++s) acc[r][s] = 0ull;

    const int kb = ks * 32;
    for (int c = 0; c < NC; ++c) {
#pragma unroll
        for (int w = 0; w < 4; ++w) {
            *reinterpret_cast<float4*>(&sA[rows[w] * PSTR + cols[w]]) = rA[w];
            *reinterpret_cast<float4*>(&sW[rows[w] * PSTR + cols[w]]) = rW[w];
        }
        __syncthreads();
        if (c + 1 < NC) load_chunk(c + 1);   // prefetch next chunk into registers

#pragma unroll
        for (int kk = 0; kk < 32; kk += 4) {
            const int kc = kb + kk;
            float4 a[4], w4[4];
#pragma unroll
            for (int r = 0; r < 4; ++r)
                a[r] = *reinterpret_cast<const float4*>(&sA[(ty + 8 * r) * PSTR + kc]);
#pragma unroll
            for (int s = 0; s < 4; ++s)
                w4[s] = *reinterpret_cast<const float4*>(&sW[(tx + 8 * s) * PSTR + kc]);

            ull al[4], ah[4], wl[4], wh[4];
#pragma unroll
            for (int r = 0; r < 4; ++r) { al[r] = pack2(a[r].x, a[r].y); ah[r] = pack2(a[r].z, a[r].w); }
#pragma unroll
            for (int s = 0; s < 4; ++s) { wl[s] = pack2(w4[s].x, w4[s].y); wh[s] = pack2(w4[s].z, w4[s].w); }
#pragma unroll
            for (int r = 0; r < 4; ++r)
#pragma unroll
                for (int s = 0; s < 4; ++s) {
                    acc[r][s] = ffma2(al[r], wl[s], acc[r][s]);
                    acc[r][s] = ffma2(ah[r], wh[s], acc[r][s]);
                }
        }
        __syncthreads();
    }

    // reduce 4 k-slices via smem (aliases sA; all tile reads are done)
    float part[16];
#pragma unroll
    for (int r = 0; r < 4; ++r)
#pragma unroll
        for (int s = 0; s < 4; ++s) part[r * 4 + s] = hsum2(acc[r][s]);

    float* sRed = smem;   // needs 4*64*16 = 4096 floats
#pragma unroll
    for (int i = 0; i < 16; ++i)
        sRed[(lid * 4 + ks) * 16 + i] = part[i];
    __syncthreads();

#pragma unroll
    for (int i = 0; i < 4; ++i) {
        const int f = tid * 4 + i;          // flat output 0..1023
        const int lsrc = f >> 4;
        const int o = f & 15;
        float pre = sRed[(lsrc * 4 + 0) * 16 + o]
                  + sRed[(lsrc * 4 + 1) * 16 + o]
                  + sRed[(lsrc * 4 + 2) * 16 + o]
                  + sRed[(lsrc * 4 + 3) * 16 + o];
        const int r = o >> 2, s = o & 3;
        const int tyS = lsrc >> 3, txS = lsrc & 7;
        const int b = b0 + tyS + 8 * r;
        const int j = j0 + txS + 8 * s;
        const float hold = hread[b * HH + j];
        const float hn = 0.5f * hold + 0.5f * tanhf(pre);
        hwrite[b * HH + j] = hn;
        out[((size_t)(step * BB + b) * 2 + layer) * HH + j] = hn;
    }
}

extern "C" void kernel_launch(void* const* d_in, const int* in_sizes, int n_in,
                              void* d_out, int out_size)
{
    const float* x     = (const float*)d_in[0];
    const float* Win0  = (const float*)d_in[1];
    const float* What0 = (const float*)d_in[2];
    const float* Win1  = (const float*)d_in[3];
    const float* What1 = (const float*)d_in[4];
    float* out = (float*)d_out;

    init_kernel<<<128, 256>>>();
    for (int ph = 0; ph <= TT; ++ph)
        step_kernel<<<128, 256>>>(x, Win0, What0, Win1, What1, out, ph);
}